// round 5
// baseline (speedup 1.0000x reference)
#include <cuda_runtime.h>
#include <math.h>

// ---------------- problem constants ----------------
#define BB 2
#define DIMC 256
#define FF 4
#define HH 16
#define WW 16
#define PQ 1024          // F*H*W
#define GR 4
#define OFFD 128
#define FD 2
#define HD 8
#define WD 8
#define PJ 128           // FD*HD*WD
#define NHEADS 8
#define DHEAD 64
#define NBG 8            // B*GROUPS

// ---------------- scratch (static device mem; no allocs) ----------------
__device__ float g_q  [NBG * OFFD * PQ];     // (bg, o, p)
__device__ float g_qT [NBG * PQ * OFFD];     // (bg, p, o)
__device__ float g_grid[NBG * PJ * 3];       // normalized grid_kv
__device__ float g_k  [BB * NHEADS * DHEAD * PJ];
__device__ float g_v  [BB * NHEADS * DHEAD * PJ];
__device__ float g_bias[2 * NBG * PQ * PJ];  // [m][n][i][j]
__device__ float g_attT[BB * PQ * 512];      // (b, p, c=h*64+d)

// ---------------- K1: grouped 1x1 conv -> q ----------------
__global__ __launch_bounds__(128) void k_qproj(const float* __restrict__ x,
                                               const float* __restrict__ wq) {
    int bg = blockIdx.y;
    int p0 = blockIdx.x * 64;
    int o  = threadIdx.x;          // 0..127
    int b = bg >> 2, g = bg & 3;

    float wr[64];
    const float4* wrow = (const float4*)(wq + (g * 128 + o) * 64);
#pragma unroll
    for (int i = 0; i < 16; i++) {
        float4 v4 = wrow[i];
        wr[i*4+0] = v4.x; wr[i*4+1] = v4.y; wr[i*4+2] = v4.z; wr[i*4+3] = v4.w;
    }

    __shared__ float xs[64 * 8];         // xs[i*8 + pp]
    const float* xb = x + (b * 256 + g * 64) * 1024 + p0;
    for (int pt = 0; pt < 64; pt += 8) {
        __syncthreads();
        for (int idx = o; idx < 512; idx += 128) {
            int i = idx >> 3, pp = idx & 7;
            xs[idx] = xb[i * 1024 + pt + pp];
        }
        __syncthreads();
#pragma unroll
        for (int pp = 0; pp < 8; pp++) {
            float s = 0.f;
#pragma unroll
            for (int i = 0; i < 64; i++) s = fmaf(wr[i], xs[i * 8 + pp], s);
            int p = p0 + pt + pp;
            g_q [(bg * 128 + o) * 1024 + p] = s;
            g_qT[(bg * 1024 + p) * 128 + o] = s;
        }
    }
}

// ---------------- K2: depthwise conv -> GELU -> pw -> tanh -> grid ----------------
__global__ __launch_bounds__(128) void k_offsets(const float* __restrict__ dww,
                                                 const float* __restrict__ dwb,
                                                 const float* __restrict__ pw) {
    int n  = blockIdx.y;
    int jj = blockIdx.x;                 // 0..127 out position, f-major
    int od = jj >> 6, oh = (jj >> 3) & 7, ow = jj & 7;
    int c  = threadIdx.x;                // channel

    const float* qb = g_q + (n * 128 + c) * 1024;
    const float* wb = dww + c * 64;
    float acc = 0.f;
#pragma unroll
    for (int kf = 0; kf < 4; kf++) {
        int fi = od * 2 - 1 + kf;
        if (fi < 0 || fi >= FF) continue;
#pragma unroll
        for (int kh = 0; kh < 4; kh++) {
            int hi = oh * 2 - 1 + kh;
            if (hi < 0 || hi >= HH) continue;
#pragma unroll
            for (int kw = 0; kw < 4; kw++) {
                int wi = ow * 2 - 1 + kw;
                if (wi < 0 || wi >= WW) continue;
                acc = fmaf(qb[fi * 256 + hi * 16 + wi], wb[kf * 16 + kh * 4 + kw], acc);
            }
        }
    }
    float v  = acc + dwb[c];
    float ge = 0.5f * v * (1.0f + erff(v * 0.70710678118654752f));   // exact GELU

    __shared__ float red[3][128];
    red[0][c] = ge * pw[c];
    red[1][c] = ge * pw[128 + c];
    red[2][c] = ge * pw[256 + c];
    __syncthreads();
    for (int s = 64; s > 0; s >>= 1) {
        if (c < s) {
            red[0][c] += red[0][c + s];
            red[1][c] += red[1][c + s];
            red[2][c] += red[2][c + s];
        }
        __syncthreads();
    }
    if (c < 3) {
        float off   = tanhf(red[c][0]) * 2.0f;
        float basec = (c == 0) ? (float)od : (c == 1) ? (float)oh : (float)ow;
        float denom = (c == 0) ? 1.0f : 7.0f;   // max(size-1,1): fd=2,hd=8,wd=8
        g_grid[(n * 128 + jj) * 3 + c] = 2.0f * (basec + off) / denom - 1.0f;
    }
}

// ---------------- K3: trilinear gather + k/v projection ----------------
__global__ __launch_bounds__(128) void k_sample(const float* __restrict__ x,
                                                const float* __restrict__ wk,
                                                const float* __restrict__ wv) {
    int n = blockIdx.y, j = blockIdx.x;
    int b = n >> 2, g = n & 3;
    int t = threadIdx.x;

    float g0 = g_grid[(n * 128 + j) * 3 + 0];
    float g1 = g_grid[(n * 128 + j) * 3 + 1];
    float g2 = g_grid[(n * 128 + j) * 3 + 2];
    // reference's grid_sample axis convention: comp0->W(16), comp1->H(16), comp2->D(4)
    float ix = ((g0 + 1.f) * 16.f - 1.f) * 0.5f;
    float iy = ((g1 + 1.f) * 16.f - 1.f) * 0.5f;
    float iz = ((g2 + 1.f) * 4.f  - 1.f) * 0.5f;
    float x0f = floorf(ix), y0f = floorf(iy), z0f = floorf(iz);
    float tx = ix - x0f, ty = iy - y0f, tz = iz - z0f;
    int x0 = (int)x0f, y0 = (int)y0f, z0 = (int)z0f;

    __shared__ float kvs[64];
    if (t < 64) {
        const float* vol = x + (b * 256 + g * 64 + t) * 1024;
        float s = 0.f;
#pragma unroll
        for (int dz = 0; dz < 2; dz++)
#pragma unroll
            for (int dy = 0; dy < 2; dy++)
#pragma unroll
                for (int dx = 0; dx < 2; dx++) {
                    int xc = x0 + dx, yc = y0 + dy, zc = z0 + dz;
                    float wgt = (dx ? tx : 1.f - tx) * (dy ? ty : 1.f - ty) * (dz ? tz : 1.f - tz);
                    if (xc >= 0 && xc < 16 && yc >= 0 && yc < 16 && zc >= 0 && zc < 4)
                        s = fmaf(vol[zc * 256 + yc * 16 + xc], wgt, s);
                }
        kvs[t] = s;
    }
    __syncthreads();

    const float* wkr = wk + (g * 128 + t) * 64;
    const float* wvr = wv + (g * 128 + t) * 64;
    float sk = 0.f, sv = 0.f;
#pragma unroll
    for (int i = 0; i < 64; i++) {
        float kv = kvs[i];
        sk = fmaf(kv, wkr[i], sk);
        sv = fmaf(kv, wvr[i], sv);
    }
    int h = g * 2 + (t >> 6);
    int d = t & 63;
    g_k[((b * 8 + h) * 64 + d) * 128 + j] = sk;
    g_v[((b * 8 + h) * 64 + d) * 128 + j] = sv;
}

// ---------------- K4: CPB bias MLP — register-blocked 8x8 GEMM, f32x2 ----------------
// Block = one (n,i) row x 128 j-pairs. Thread (tp,tc) computes 8 pairs x 8 channels.
__global__ __launch_bounds__(128, 4) void k_cpb(const float* __restrict__ w0,
                                                const float* __restrict__ b0,
                                                const float* __restrict__ w1,
                                                const float* __restrict__ b1,
                                                const float* __restrict__ w2,
                                                const float* __restrict__ b2) {
    __shared__ __align__(16) float w1s[4096];       // [k][c]
    __shared__ __align__(16) float h0s[32 * 136];   // [kk][pair], half of k at a time
    __shared__ float w0s[192], b0s[64], b1s[64], w2s[128], b2s[2];
    int tid = threadIdx.x;
    for (int idx = tid; idx < 4096; idx += 128) w1s[idx] = w1[idx];
    for (int idx = tid; idx < 192;  idx += 128) w0s[idx] = w0[idx];
    if (tid < 64) { b0s[tid] = b0[tid]; b1s[tid] = b1[tid]; }
    w2s[tid] = w2[tid];
    if (tid < 2) b2s[tid] = b2[tid];

    int base = blockIdx.x * 128;             // all 128 pairs share (n, i)
    int n = base >> 17;
    int i = (base >> 7) & 1023;

    // features for this thread's own pair j = tid (used in phase 1)
    float t0, t1, t2;
    {
        float gq0 = 2.f * (float)(i >> 8)        / 3.f  - 1.f;
        float gq1 = 2.f * (float)((i >> 4) & 15) / 15.f - 1.f;
        float gq2 = 2.f * (float)(i & 15)        / 15.f - 1.f;
        float p0 = gq0 - g_grid[(n * 128 + tid) * 3 + 0];
        float p1 = gq1 - g_grid[(n * 128 + tid) * 3 + 1];
        float p2 = gq2 - g_grid[(n * 128 + tid) * 3 + 2];
        t0 = copysignf(log1pf(fabsf(p0)), p0);
        t1 = copysignf(log1pf(fabsf(p1)), p1);
        t2 = copysignf(log1pf(fabsf(p2)), p2);
    }

    int tc = tid & 7;        // channel group: ch = tc*8 .. tc*8+7
    int tp = tid >> 3;       // pair group:   pr = tp*8 .. tp*8+7
    __syncthreads();

    // acc[p][c2]: pair p (0..7), channel f32x2 pair c2 (0..3) -> ch (tc*8+2c2, +1)
    unsigned long long acc[32];
#pragma unroll
    for (int c2 = 0; c2 < 4; c2++) {
        unsigned long long bi;
        asm("mov.b64 %0, {%1, %2};" : "=l"(bi)
            : "f"(b1s[tc * 8 + 2 * c2]), "f"(b1s[tc * 8 + 2 * c2 + 1]));
#pragma unroll
        for (int p = 0; p < 8; p++) acc[p * 4 + c2] = bi;
    }

#pragma unroll
    for (int half = 0; half < 2; half++) {
        int k0 = half * 32;
        // phase 1: layer-0 for own pair, k in [k0, k0+32)
#pragma unroll 8
        for (int kk = 0; kk < 32; kk++) {
            int k = k0 + kk;
            float h = fmaxf(fmaf(t0, w0s[k], fmaf(t1, w0s[64 + k],
                           fmaf(t2, w0s[128 + k], b0s[k]))), 0.f);
            h0s[kk * 136 + tid] = h;
        }
        __syncthreads();
        // phase 2: 8x8 register-tile GEMM over this k half
#pragma unroll 4
        for (int kk = 0; kk < 32; kk++) {
            int k = k0 + kk;
            const float4* hp = (const float4*)&h0s[kk * 136 + tp * 8];
            float4 ha = hp[0], hb = hp[1];
            const ulonglong2* wp = (const ulonglong2*)&w1s[k * 64 + tc * 8];
            ulonglong2 wlo = wp[0], whi = wp[1];   // w01,w23 / w45,w67 as f32x2
            float hv[8] = {ha.x, ha.y, ha.z, ha.w, hb.x, hb.y, hb.z, hb.w};
#pragma unroll
            for (int p = 0; p < 8; p++) {
                unsigned long long h2;
                asm("mov.b64 %0, {%1, %1};" : "=l"(h2) : "f"(hv[p]));
                asm("fma.rn.f32x2 %0, %1, %2, %0;" : "+l"(acc[p*4+0]) : "l"(h2), "l"(wlo.x));
                asm("fma.rn.f32x2 %0, %1, %2, %0;" : "+l"(acc[p*4+1]) : "l"(h2), "l"(wlo.y));
                asm("fma.rn.f32x2 %0, %1, %2, %0;" : "+l"(acc[p*4+2]) : "l"(h2), "l"(whi.x));
                asm("fma.rn.f32x2 %0, %1, %2, %0;" : "+l"(acc[p*4+3]) : "l"(h2), "l"(whi.y));
            }
        }
        __syncthreads();
    }

    // epilogue: relu + partial layer-2 over own 8 channels, reduce over tc lanes
    float o0[8], o1[8];
#pragma unroll
    for (int p = 0; p < 8; p++) {
        float s0 = 0.f, s1 = 0.f;
#pragma unroll
        for (int c2 = 0; c2 < 4; c2++) {
            float lo, hi;
            asm("mov.b64 {%0, %1}, %2;" : "=f"(lo), "=f"(hi) : "l"(acc[p * 4 + c2]));
            lo = fmaxf(lo, 0.f); hi = fmaxf(hi, 0.f);
            int ch = tc * 8 + 2 * c2;
            s0 = fmaf(lo, w2s[ch * 2 + 0], s0);
            s1 = fmaf(lo, w2s[ch * 2 + 1], s1);
            s0 = fmaf(hi, w2s[ch * 2 + 2], s0);
            s1 = fmaf(hi, w2s[ch * 2 + 3], s1);
        }
        o0[p] = s0; o1[p] = s1;
    }
#pragma unroll
    for (int off = 1; off < 8; off <<= 1) {
#pragma unroll
        for (int p = 0; p < 8; p++) {
            o0[p] += __shfl_xor_sync(0xffffffff, o0[p], off);
            o1[p] += __shfl_xor_sync(0xffffffff, o1[p], off);
        }
    }
    if (tc == 0) {
        float* b0p = g_bias + (        n * 1024 + i) * 128 + tp * 8;
        float* b1p = g_bias + ((8 + n) * 1024 + i) * 128 + tp * 8;
#pragma unroll
        for (int p = 0; p < 8; p++) {
            b0p[p] = o0[p] + b2s[0];
            b1p[p] = o1[p] + b2s[1];
        }
    }
}

// ---------------- K5: attention — K in registers, V in shared ----------------
__global__ __launch_bounds__(128) void k_attn() {
    int b = blockIdx.z, h = blockIdx.y;
    int i0 = blockIdx.x * 16;
    int g = h >> 1, m = h & 1;
    int n = b * 4 + g;
    int t = threadIdx.x;
    int lane = t & 31, warp = t >> 5;

    __shared__ float vs[64 * 129];          // padded: row stride 129
    __shared__ __align__(16) float qs[64];
    __shared__ float attn[128];
    __shared__ float wred[8];
    __shared__ float ored[128];

    const float* kb = g_k + (b * 8 + h) * 64 * 128;
    const float* vb = g_v + (b * 8 + h) * 64 * 128;

    // K column for this thread's j=t, kept in registers (read from gmem ONCE)
    float kreg[64];
#pragma unroll
    for (int d = 0; d < 64; d++) kreg[d] = kb[d * 128 + t];

    for (int idx = t; idx < 8192; idx += 128) {
        int d = idx >> 7, jc = idx & 127;
        vs[d * 129 + jc] = vb[idx];
    }
    const float* biasrow = g_bias + ((m * 8 + n) * 1024) * 128;

    for (int ii = 0; ii < 16; ii++) {
        int i = i0 + ii;
        __syncthreads();
        if (t < 64) qs[t] = g_qT[((b * 4 + g) * 1024 + i) * 128 + m * 64 + t];
        __syncthreads();

        float s = 0.f;
        const float4* q4 = (const float4*)qs;
#pragma unroll
        for (int dd = 0; dd < 16; dd++) {
            float4 qv = q4[dd];
            s = fmaf(qv.x, kreg[dd * 4 + 0], s);
            s = fmaf(qv.y, kreg[dd * 4 + 1], s);
            s = fmaf(qv.z, kreg[dd * 4 + 2], s);
            s = fmaf(qv.w, kreg[dd * 4 + 3], s);
        }
        s = fmaf(s, 0.125f, biasrow[i * 128 + t]);

        // max over 128
        float lm = s;
#pragma unroll
        for (int o = 16; o > 0; o >>= 1) lm = fmaxf(lm, __shfl_xor_sync(0xffffffff, lm, o));
        if (lane == 0) wred[warp] = lm;
        __syncthreads();
        float mx = fmaxf(fmaxf(wred[0], wred[1]), fmaxf(wred[2], wred[3]));

        float e = __expf(s - mx);
        attn[t] = e;
        float ls = e;
#pragma unroll
        for (int o = 16; o > 0; o >>= 1) ls += __shfl_xor_sync(0xffffffff, ls, o);
        if (lane == 0) wred[4 + warp] = ls;
        __syncthreads();
        float inv = 1.f / (wred[4] + wred[5] + wred[6] + wred[7]);

        // out[d] = sum_j attn[j] * v[d][j]
        int d = t & 63, half = t >> 6;
        const float* vrow = vs + d * 129 + half * 64;
        const float* arow = attn + half * 64;
        float acc = 0.f;
#pragma unroll
        for (int jj = 0; jj < 64; jj++) acc = fmaf(arow[jj], vrow[jj], acc);
        ored[t] = acc;
        __syncthreads();
        if (t < 64)
            g_attT[(b * 1024 + i) * 512 + h * 64 + t] = (ored[t] + ored[64 + t]) * inv;
    }
}

// ---------------- K6: output projection — 2x2 register blocking ----------------
__global__ __launch_bounds__(256) void k_outproj(const float* __restrict__ wo,
                                                 const float* __restrict__ bo,
                                                 float* __restrict__ out) {
    int b  = blockIdx.z;
    int ty = threadIdx.y, tx = threadIdx.x;
    int o0 = blockIdx.y * 32;
    int p0 = blockIdx.x * 32;

    __shared__ float wos[32][17];
    __shared__ float ats[32][17];
    float a00 = 0.f, a01 = 0.f, a10 = 0.f, a11 = 0.f;
    for (int kt = 0; kt < 32; kt++) {
        wos[ty]     [tx] = wo[(o0 + ty)      * 512 + kt * 16 + tx];
        wos[ty + 16][tx] = wo[(o0 + ty + 16) * 512 + kt * 16 + tx];
        ats[ty]     [tx] = g_attT[(b * 1024 + p0 + ty)      * 512 + kt * 16 + tx];
        ats[ty + 16][tx] = g_attT[(b * 1024 + p0 + ty + 16) * 512 + kt * 16 + tx];
        __syncthreads();
#pragma unroll
        for (int kk = 0; kk < 16; kk++) {
            float wa = wos[ty][kk],      wb2 = wos[ty + 16][kk];
            float pa = ats[tx][kk],      pb  = ats[tx + 16][kk];
            a00 = fmaf(wa,  pa, a00);
            a01 = fmaf(wa,  pb, a01);
            a10 = fmaf(wb2, pa, a10);
            a11 = fmaf(wb2, pb, a11);
        }
        __syncthreads();
    }
    float bo0 = bo[o0 + ty], bo1 = bo[o0 + ty + 16];
    out[(b * 256 + o0 + ty)      * 1024 + p0 + tx]      = a00 + bo0;
    out[(b * 256 + o0 + ty)      * 1024 + p0 + tx + 16] = a01 + bo0;
    out[(b * 256 + o0 + ty + 16) * 1024 + p0 + tx]      = a10 + bo1;
    out[(b * 256 + o0 + ty + 16) * 1024 + p0 + tx + 16] = a11 + bo1;
}

// ---------------- launch ----------------
extern "C" void kernel_launch(void* const* d_in, const int* in_sizes, int n_in,
                              void* d_out, int out_size) {
    const float* x      = (const float*)d_in[0];
    const float* wq     = (const float*)d_in[1];
    const float* wk     = (const float*)d_in[2];
    const float* wv     = (const float*)d_in[3];
    const float* dww    = (const float*)d_in[4];
    const float* dwb    = (const float*)d_in[5];
    const float* pw     = (const float*)d_in[6];
    const float* cw0    = (const float*)d_in[7];
    const float* cb0    = (const float*)d_in[8];
    const float* cw1    = (const float*)d_in[9];
    const float* cb1    = (const float*)d_in[10];
    const float* cw2    = (const float*)d_in[11];
    const float* cb2    = (const float*)d_in[12];
    const float* wo     = (const float*)d_in[13];
    const float* bo     = (const float*)d_in[14];
    float* out = (float*)d_out;

    k_qproj  <<<dim3(16, 8),       128>>>(x, wq);
    k_offsets<<<dim3(128, 8),      128>>>(dww, dwb, pw);
    k_sample <<<dim3(128, 8),      128>>>(x, wk, wv);
    k_cpb    <<<8192,              128>>>(cw0, cb0, cw1, cb1, cw2, cb2);
    k_attn   <<<dim3(64, 8, 2),    128>>>();
    k_outproj<<<dim3(32, 8, 2), dim3(16, 16)>>>(wo, bo, out);
}

// round 8
// speedup vs baseline: 1.7013x; 1.7013x over previous
#include <cuda_runtime.h>
#include <math.h>

// ---------------- problem constants ----------------
#define BB 2
#define PQ 1024
#define PJ 128
#define NBG 8

// ---------------- scratch (static device mem; no allocs) ----------------
__device__ float g_q  [NBG * 128 * PQ];      // (bg, o, p)
__device__ float g_qT [NBG * PQ * 128];      // (bg, p, o)
__device__ float g_grid[NBG * PJ * 3];       // normalized grid_kv
__device__ float g_k  [BB * 8 * 64 * PJ];
__device__ float g_v  [BB * 8 * 64 * PJ];
__device__ float g_bias[2 * NBG * PQ * PJ];  // [m][n][i][j]
__device__ float g_attT[BB * PQ * 512];      // (b, p, c=h*64+d)

// ---------------- K1: grouped 1x1 conv -> q (batched 8 p / barrier) ----------------
__global__ __launch_bounds__(128) void k_qproj(const float* __restrict__ x,
                                               const float* __restrict__ wq) {
    int bg = blockIdx.y;
    int p0 = blockIdx.x * 64;
    int o  = threadIdx.x;
    int b = bg >> 2, g = bg & 3;

    float wr[64];
    const float4* wrow = (const float4*)(wq + (g * 128 + o) * 64);
#pragma unroll
    for (int i = 0; i < 16; i++) {
        float4 v4 = wrow[i];
        wr[i*4+0] = v4.x; wr[i*4+1] = v4.y; wr[i*4+2] = v4.z; wr[i*4+3] = v4.w;
    }

    __shared__ float xs[64 * 8];
    const float* xb = x + (b * 256 + g * 64) * 1024 + p0;
    for (int pt = 0; pt < 64; pt += 8) {
        __syncthreads();
        for (int idx = o; idx < 512; idx += 128) {
            int i = idx >> 3, pp = idx & 7;
            xs[idx] = xb[i * 1024 + pt + pp];
        }
        __syncthreads();
#pragma unroll
        for (int pp = 0; pp < 8; pp++) {
            float s = 0.f;
#pragma unroll
            for (int i = 0; i < 64; i++) s = fmaf(wr[i], xs[i * 8 + pp], s);
            int p = p0 + pt + pp;
            g_q [(bg * 128 + o) * 1024 + p] = s;
            g_qT[(bg * 1024 + p) * 128 + o] = s;
        }
    }
}

// ---------------- K2: depthwise conv -> GELU -> pw -> tanh -> grid ----------------
__global__ __launch_bounds__(128) void k_offsets(const float* __restrict__ dww,
                                                 const float* __restrict__ dwb,
                                                 const float* __restrict__ pw) {
    int n  = blockIdx.y;
    int jj = blockIdx.x;
    int od = jj >> 6, oh = (jj >> 3) & 7, ow = jj & 7;
    int c  = threadIdx.x;

    const float* qb = g_q + (n * 128 + c) * 1024;
    const float* wb = dww + c * 64;
    float acc = 0.f;
#pragma unroll
    for (int kf = 0; kf < 4; kf++) {
        int fi = od * 2 - 1 + kf;
        if (fi < 0 || fi >= 4) continue;
#pragma unroll
        for (int kh = 0; kh < 4; kh++) {
            int hi = oh * 2 - 1 + kh;
            if (hi < 0 || hi >= 16) continue;
#pragma unroll
            for (int kw = 0; kw < 4; kw++) {
                int wi = ow * 2 - 1 + kw;
                if (wi < 0 || wi >= 16) continue;
                acc = fmaf(qb[fi * 256 + hi * 16 + wi], wb[kf * 16 + kh * 4 + kw], acc);
            }
        }
    }
    float v  = acc + dwb[c];
    float ge = 0.5f * v * (1.0f + erff(v * 0.70710678118654752f));   // exact GELU

    __shared__ float red[3][128];
    red[0][c] = ge * pw[c];
    red[1][c] = ge * pw[128 + c];
    red[2][c] = ge * pw[256 + c];
    __syncthreads();
    for (int s = 64; s > 0; s >>= 1) {
        if (c < s) {
            red[0][c] += red[0][c + s];
            red[1][c] += red[1][c + s];
            red[2][c] += red[2][c + s];
        }
        __syncthreads();
    }
    if (c < 3) {
        float off   = tanhf(red[c][0]) * 2.0f;
        float basec = (c == 0) ? (float)od : (c == 1) ? (float)oh : (float)ow;
        float denom = (c == 0) ? 1.0f : 7.0f;
        g_grid[(n * 128 + jj) * 3 + c] = 2.0f * (basec + off) / denom - 1.0f;
    }
}

// ---------------- K3: trilinear gather + k/v projection ----------------
__global__ __launch_bounds__(128) void k_sample(const float* __restrict__ x,
                                                const float* __restrict__ wk,
                                                const float* __restrict__ wv) {
    int n = blockIdx.y, j = blockIdx.x;
    int b = n >> 2, g = n & 3;
    int t = threadIdx.x;

    float g0 = g_grid[(n * 128 + j) * 3 + 0];
    float g1 = g_grid[(n * 128 + j) * 3 + 1];
    float g2 = g_grid[(n * 128 + j) * 3 + 2];
    // reference's grid_sample axis convention: comp0->W(16), comp1->H(16), comp2->D(4)
    float ix = ((g0 + 1.f) * 16.f - 1.f) * 0.5f;
    float iy = ((g1 + 1.f) * 16.f - 1.f) * 0.5f;
    float iz = ((g2 + 1.f) * 4.f  - 1.f) * 0.5f;
    float x0f = floorf(ix), y0f = floorf(iy), z0f = floorf(iz);
    float tx = ix - x0f, ty = iy - y0f, tz = iz - z0f;
    int x0 = (int)x0f, y0 = (int)y0f, z0 = (int)z0f;

    __shared__ float kvs[64];
    if (t < 64) {
        const float* vol = x + (b * 256 + g * 64 + t) * 1024;
        float s = 0.f;
#pragma unroll
        for (int dz = 0; dz < 2; dz++)
#pragma unroll
            for (int dy = 0; dy < 2; dy++)
#pragma unroll
                for (int dx = 0; dx < 2; dx++) {
                    int xc = x0 + dx, yc = y0 + dy, zc = z0 + dz;
                    float wgt = (dx ? tx : 1.f - tx) * (dy ? ty : 1.f - ty) * (dz ? tz : 1.f - tz);
                    if (xc >= 0 && xc < 16 && yc >= 0 && yc < 16 && zc >= 0 && zc < 4)
                        s = fmaf(vol[zc * 256 + yc * 16 + xc], wgt, s);
                }
        kvs[t] = s;
    }
    __syncthreads();

    const float* wkr = wk + (g * 128 + t) * 64;
    const float* wvr = wv + (g * 128 + t) * 64;
    float sk = 0.f, sv = 0.f;
#pragma unroll
    for (int i = 0; i < 64; i++) {
        float kv = kvs[i];
        sk = fmaf(kv, wkr[i], sk);
        sv = fmaf(kv, wvr[i], sv);
    }
    int h = g * 2 + (t >> 6);
    int d = t & 63;
    g_k[((b * 8 + h) * 64 + d) * 128 + j] = sk;
    g_v[((b * 8 + h) * 64 + d) * 128 + j] = sv;
}

// ---------------- K4: CPB bias MLP — f32x2 packed, 2 pairs/thread (best measured: 211us) ----------------
__global__ __launch_bounds__(256, 1) void k_cpb(const float* __restrict__ w0,
                                                const float* __restrict__ b0,
                                                const float* __restrict__ w1,
                                                const float* __restrict__ b1,
                                                const float* __restrict__ w2,
                                                const float* __restrict__ b2) {
    __shared__ __align__(16) float w1s[4096];
    __shared__ float w0s[192], b0s[64], b1s[64], w2s[128], b2s[2];
    int tid = threadIdx.x;
    for (int i = tid; i < 192;  i += 256) w0s[i] = w0[i];
    for (int i = tid; i < 64;   i += 256) { b0s[i] = b0[i]; b1s[i] = b1[i]; }
    for (int i = tid; i < 4096; i += 256) w1s[i] = w1[i];
    for (int i = tid; i < 128;  i += 256) w2s[i] = w2[i];
    if (tid < 2) b2s[tid] = b2[tid];
    __syncthreads();

    // two pairs per thread: pa and pb = pa + 256
    int pa = blockIdx.x * 512 + tid;
    int pb = pa + 256;

    float ta0, ta1, ta2, tb0, tb1, tb2;
    {
        int n = pa >> 17, i = (pa >> 7) & 1023, j = pa & 127;
        float gq0 = 2.f * (float)(i >> 8)        / 3.f  - 1.f;
        float gq1 = 2.f * (float)((i >> 4) & 15) / 15.f - 1.f;
        float gq2 = 2.f * (float)(i & 15)        / 15.f - 1.f;
        float p0 = gq0 - g_grid[(n * 128 + j) * 3 + 0];
        float p1 = gq1 - g_grid[(n * 128 + j) * 3 + 1];
        float p2 = gq2 - g_grid[(n * 128 + j) * 3 + 2];
        ta0 = copysignf(log1pf(fabsf(p0)), p0);
        ta1 = copysignf(log1pf(fabsf(p1)), p1);
        ta2 = copysignf(log1pf(fabsf(p2)), p2);
    }
    {
        int n = pb >> 17, i = (pb >> 7) & 1023, j = pb & 127;
        float gq0 = 2.f * (float)(i >> 8)        / 3.f  - 1.f;
        float gq1 = 2.f * (float)((i >> 4) & 15) / 15.f - 1.f;
        float gq2 = 2.f * (float)(i & 15)        / 15.f - 1.f;
        float p0 = gq0 - g_grid[(n * 128 + j) * 3 + 0];
        float p1 = gq1 - g_grid[(n * 128 + j) * 3 + 1];
        float p2 = gq2 - g_grid[(n * 128 + j) * 3 + 2];
        tb0 = copysignf(log1pf(fabsf(p0)), p0);
        tb1 = copysignf(log1pf(fabsf(p1)), p1);
        tb2 = copysignf(log1pf(fabsf(p2)), p2);
    }

    // accumulators: channel pairs (2c, 2c+1) packed as f32x2
    unsigned long long acc_a[32], acc_b[32];
#pragma unroll
    for (int c = 0; c < 32; c++) {
        unsigned long long bi;
        asm("mov.b64 %0, {%1, %2};" : "=l"(bi) : "f"(b1s[2 * c]), "f"(b1s[2 * c + 1]));
        acc_a[c] = bi;
        acc_b[c] = bi;
    }

#pragma unroll 4
    for (int k = 0; k < 64; k++) {
        float w0k = w0s[k], w1k = w0s[64 + k], w2k = w0s[128 + k], b0k = b0s[k];
        float ha = fmaxf(fmaf(ta0, w0k, fmaf(ta1, w1k, fmaf(ta2, w2k, b0k))), 0.f);
        float hb = fmaxf(fmaf(tb0, w0k, fmaf(tb1, w1k, fmaf(tb2, w2k, b0k))), 0.f);
        unsigned long long ha2, hb2;
        asm("mov.b64 %0, {%1, %1};" : "=l"(ha2) : "f"(ha));
        asm("mov.b64 %0, {%1, %1};" : "=l"(hb2) : "f"(hb));
        const ulonglong2* wrow = (const ulonglong2*)(w1s + k * 64);
#pragma unroll
        for (int c = 0; c < 16; c++) {
            ulonglong2 wv = wrow[c];      // LDS.128 broadcast -> two f32x2 operands
            asm("fma.rn.f32x2 %0, %1, %2, %0;" : "+l"(acc_a[2 * c])     : "l"(ha2), "l"(wv.x));
            asm("fma.rn.f32x2 %0, %1, %2, %0;" : "+l"(acc_a[2 * c + 1]) : "l"(ha2), "l"(wv.y));
            asm("fma.rn.f32x2 %0, %1, %2, %0;" : "+l"(acc_b[2 * c])     : "l"(hb2), "l"(wv.x));
            asm("fma.rn.f32x2 %0, %1, %2, %0;" : "+l"(acc_b[2 * c + 1]) : "l"(hb2), "l"(wv.y));
        }
    }

    // epilogue: relu -> w2 (64 -> 2) for each pair, store
    {
        float o0 = b2s[0], o1 = b2s[1];
#pragma unroll
        for (int c = 0; c < 32; c++) {
            float lo, hi;
            asm("mov.b64 {%0, %1}, %2;" : "=f"(lo), "=f"(hi) : "l"(acc_a[c]));
            lo = fmaxf(lo, 0.f); hi = fmaxf(hi, 0.f);
            o0 = fmaf(lo, w2s[4 * c + 0], o0);
            o1 = fmaf(lo, w2s[4 * c + 1], o1);
            o0 = fmaf(hi, w2s[4 * c + 2], o0);
            o1 = fmaf(hi, w2s[4 * c + 3], o1);
        }
        int n = pa >> 17, i = (pa >> 7) & 1023, j = pa & 127;
        g_bias[(        n * 1024 + i) * 128 + j] = o0;
        g_bias[((8 + n) * 1024 + i) * 128 + j]   = o1;
    }
    {
        float o0 = b2s[0], o1 = b2s[1];
#pragma unroll
        for (int c = 0; c < 32; c++) {
            float lo, hi;
            asm("mov.b64 {%0, %1}, %2;" : "=f"(lo), "=f"(hi) : "l"(acc_b[c]));
            lo = fmaxf(lo, 0.f); hi = fmaxf(hi, 0.f);
            o0 = fmaf(lo, w2s[4 * c + 0], o0);
            o1 = fmaf(lo, w2s[4 * c + 1], o1);
            o0 = fmaf(hi, w2s[4 * c + 2], o0);
            o1 = fmaf(hi, w2s[4 * c + 3], o1);
        }
        int n = pb >> 17, i = (pb >> 7) & 1023, j = pb & 127;
        g_bias[(        n * 1024 + i) * 128 + j] = o0;
        g_bias[((8 + n) * 1024 + i) * 128 + j]   = o1;
    }
}

// ---------------- K5: attention — K in registers, V in shared ----------------
__global__ __launch_bounds__(128) void k_attn() {
    int b = blockIdx.z, h = blockIdx.y;
    int i0 = blockIdx.x * 16;
    int g = h >> 1, m = h & 1;
    int n = b * 4 + g;
    int t = threadIdx.x;
    int lane = t & 31, warp = t >> 5;

    __shared__ float vs[64 * 129];
    __shared__ __align__(16) float qs[64];
    __shared__ float attn[128];
    __shared__ float wred[8];
    __shared__ float ored[128];

    const float* kb = g_k + (b * 8 + h) * 64 * 128;
    const float* vb = g_v + (b * 8 + h) * 64 * 128;

    float kreg[64];
#pragma unroll
    for (int d = 0; d < 64; d++) kreg[d] = kb[d * 128 + t];

    for (int idx = t; idx < 8192; idx += 128) {
        int d = idx >> 7, jc = idx & 127;
        vs[d * 129 + jc] = vb[idx];
    }
    const float* biasrow = g_bias + ((m * 8 + n) * 1024) * 128;

    for (int ii = 0; ii < 16; ii++) {
        int i = i0 + ii;
        __syncthreads();
        if (t < 64) qs[t] = g_qT[((b * 4 + g) * 1024 + i) * 128 + m * 64 + t];
        __syncthreads();

        float s = 0.f;
        const float4* q4 = (const float4*)qs;
#pragma unroll
        for (int dd = 0; dd < 16; dd++) {
            float4 qv = q4[dd];
            s = fmaf(qv.x, kreg[dd * 4 + 0], s);
            s = fmaf(qv.y, kreg[dd * 4 + 1], s);
            s = fmaf(qv.z, kreg[dd * 4 + 2], s);
            s = fmaf(qv.w, kreg[dd * 4 + 3], s);
        }
        s = fmaf(s, 0.125f, biasrow[i * 128 + t]);

        float lm = s;
#pragma unroll
        for (int o = 16; o > 0; o >>= 1) lm = fmaxf(lm, __shfl_xor_sync(0xffffffff, lm, o));
        if (lane == 0) wred[warp] = lm;
        __syncthreads();
        float mx = fmaxf(fmaxf(wred[0], wred[1]), fmaxf(wred[2], wred[3]));

        float e = __expf(s - mx);
        attn[t] = e;
        float ls = e;
#pragma unroll
        for (int o = 16; o > 0; o >>= 1) ls += __shfl_xor_sync(0xffffffff, ls, o);
        if (lane == 0) wred[4 + warp] = ls;
        __syncthreads();
        float inv = 1.f / (wred[4] + wred[5] + wred[6] + wred[7]);

        int d = t & 63, half = t >> 6;
        const float* vrow = vs + d * 129 + half * 64;
        const float* arow = attn + half * 64;
        float acc = 0.f;
#pragma unroll
        for (int jj = 0; jj < 64; jj++) acc = fmaf(arow[jj], vrow[jj], acc);
        ored[t] = acc;
        __syncthreads();
        if (t < 64)
            g_attT[(b * 1024 + i) * 512 + h * 64 + t] = (ored[t] + ored[64 + t]) * inv;
    }
}

// ---------------- K6: output projection — 2x2 register blocking ----------------
__global__ __launch_bounds__(256) void k_outproj(const float* __restrict__ wo,
                                                 const float* __restrict__ bo,
                                                 float* __restrict__ out) {
    int b  = blockIdx.z;
    int ty = threadIdx.y, tx = threadIdx.x;
    int o0 = blockIdx.y * 32;
    int p0 = blockIdx.x * 32;

    __shared__ float wos[32][17];
    __shared__ float ats[32][17];
    float a00 = 0.f, a01 = 0.f, a10 = 0.f, a11 = 0.f;
    for (int kt = 0; kt < 32; kt++) {
        wos[ty]     [tx] = wo[(o0 + ty)      * 512 + kt * 16 + tx];
        wos[ty + 16][tx] = wo[(o0 + ty + 16) * 512 + kt * 16 + tx];
        ats[ty]     [tx] = g_attT[(b * 1024 + p0 + ty)      * 512 + kt * 16 + tx];
        ats[ty + 16][tx] = g_attT[(b * 1024 + p0 + ty + 16) * 512 + kt * 16 + tx];
        __syncthreads();
#pragma unroll
        for (int kk = 0; kk < 16; kk++) {
            float wa = wos[ty][kk],      wb2 = wos[ty + 16][kk];
            float pa = ats[tx][kk],      pb  = ats[tx + 16][kk];
            a00 = fmaf(wa,  pa, a00);
            a01 = fmaf(wa,  pb, a01);
            a10 = fmaf(wb2, pa, a10);
            a11 = fmaf(wb2, pb, a11);
        }
        __syncthreads();
    }
    float bo0 = bo[o0 + ty], bo1 = bo[o0 + ty + 16];
    out[(b * 256 + o0 + ty)      * 1024 + p0 + tx]      = a00 + bo0;
    out[(b * 256 + o0 + ty)      * 1024 + p0 + tx + 16] = a01 + bo0;
    out[(b * 256 + o0 + ty + 16) * 1024 + p0 + tx]      = a10 + bo1;
    out[(b * 256 + o0 + ty + 16) * 1024 + p0 + tx + 16] = a11 + bo1;
}

// ---------------- launch ----------------
extern "C" void kernel_launch(void* const* d_in, const int* in_sizes, int n_in,
                              void* d_out, int out_size) {
    const float* x      = (const float*)d_in[0];
    const float* wq     = (const float*)d_in[1];
    const float* wk     = (const float*)d_in[2];
    const float* wv     = (const float*)d_in[3];
    const float* dww    = (const float*)d_in[4];
    const float* dwb    = (const float*)d_in[5];
    const float* pw     = (const float*)d_in[6];
    const float* cw0    = (const float*)d_in[7];
    const float* cb0    = (const float*)d_in[8];
    const float* cw1    = (const float*)d_in[9];
    const float* cb1    = (const float*)d_in[10];
    const float* cw2    = (const float*)d_in[11];
    const float* cb2    = (const float*)d_in[12];
    const float* wo     = (const float*)d_in[13];
    const float* bo     = (const float*)d_in[14];
    float* out = (float*)d_out;

    k_qproj  <<<dim3(16, 8),       128>>>(x, wq);
    k_offsets<<<dim3(128, 8),      128>>>(dww, dwb, pw);
    k_sample <<<dim3(128, 8),      128>>>(x, wk, wv);
    k_cpb    <<<2048,              256>>>(cw0, cb0, cw1, cb1, cw2, cb2);
    k_attn   <<<dim3(64, 8, 2),    128>>>();
    k_outproj<<<dim3(32, 8, 2), dim3(16, 16)>>>(wo, bo, out);
}